// round 1
// baseline (speedup 1.0000x reference)
#include <cuda_runtime.h>
#include <math.h>

#define N_ADDR 150000
#define N_TX   200000
#define HID    32
#define E_AT   1000000
#define E_TA   1000000
#define E_AA   500000
#define SLOPE  0.2f
#define TB     256

// ---------------------------------------------------------------------------
// Scratch (device global — no runtime allocation)
// ---------------------------------------------------------------------------
struct __align__(128) Scratch {
    float ha [N_ADDR * HID];   // projected addr features
    float ht [N_TX   * HID];   // projected tx features
    float A  [N_ADDR * HID];   // semantic-combined addr features (layer input)
    float otx[N_TX   * HID];   // relation output at->tx  (raw, pre-relu)
    float oa1[N_ADDR * HID];   // relation output ta->addr
    float oa2[N_ADDR * HID];   // relation output aa->addr
    float as_at[N_ADDR * 4];   // alpha_src / alpha_dst per relation
    float ad_at[N_TX   * 4];
    float as_ta[N_TX   * 4];
    float ad_ta[N_ADDR * 4];
    float as_aa[N_ADDR * 4];
    float ad_aa[N_ADDR * 4];
    float s_tx[N_TX   * 4];    // softmax denominators
    float s_a1[N_ADDR * 4];
    float s_a2[N_ADDR * 4];
    float sem[64];             // semantic tanh sums [2][32]
    float attn[2];             // semantic attention weights
};
__device__ Scratch g_scr;

__device__ __forceinline__ float leaky(float v) { return v >= 0.f ? v : SLOPE * v; }

__device__ __forceinline__ void atomicAdd4(float* p, float x, float y, float z, float w) {
#if __CUDA_ARCH__ >= 900
    atomicAdd(reinterpret_cast<float4*>(p), make_float4(x, y, z, w));
#else
    atomicAdd(p + 0, x); atomicAdd(p + 1, y); atomicAdd(p + 2, z); atomicAdd(p + 3, w);
#endif
}

// ---------------------------------------------------------------------------
// Projection: h = (relu?)x @ W + b, reshaped [N,4,8]; fused alpha dot-products
// against up to 4 attention vectors (32 floats each).
// ---------------------------------------------------------------------------
__global__ void proj_kernel(const float* __restrict__ x, int N, int Fin,
                            const float* __restrict__ W, const float* __restrict__ b,
                            float* __restrict__ h,
                            const float* __restrict__ att0, float* __restrict__ ao0,
                            const float* __restrict__ att1, float* __restrict__ ao1,
                            const float* __restrict__ att2, float* __restrict__ ao2,
                            const float* __restrict__ att3, float* __restrict__ ao3,
                            int relu_in)
{
    __shared__ float sW[64 * HID];
    __shared__ float sb[HID];
    __shared__ float satt[4][HID];
    int tid = threadIdx.x;
    for (int i = tid; i < Fin * HID; i += blockDim.x) sW[i] = W[i];
    if (tid < HID) {
        sb[tid]      = b[tid];
        satt[0][tid] = att0 ? att0[tid] : 0.f;
        satt[1][tid] = att1 ? att1[tid] : 0.f;
        satt[2][tid] = att2 ? att2[tid] : 0.f;
        satt[3][tid] = att3 ? att3[tid] : 0.f;
    }
    __syncthreads();
    int n = blockIdx.x * blockDim.x + tid;
    if (n >= N) return;

    float acc[HID];
#pragma unroll
    for (int c = 0; c < HID; c++) acc[c] = sb[c];
    const float* xr = x + (size_t)n * Fin;
    for (int k = 0; k < Fin; k++) {
        float xv = xr[k];
        if (relu_in) xv = fmaxf(xv, 0.f);
#pragma unroll
        for (int c = 0; c < HID; c++) acc[c] = fmaf(xv, sW[k * HID + c], acc[c]);
    }
    float4* hv = reinterpret_cast<float4*>(h + (size_t)n * HID);
#pragma unroll
    for (int j = 0; j < 8; j++)
        hv[j] = make_float4(acc[4*j], acc[4*j+1], acc[4*j+2], acc[4*j+3]);

    float al[4][4];
#pragma unroll
    for (int hh = 0; hh < 4; hh++) {
        float s0 = 0.f, s1 = 0.f, s2 = 0.f, s3 = 0.f;
#pragma unroll
        for (int d = 0; d < 8; d++) {
            float v = acc[hh * 8 + d];
            s0 = fmaf(v, satt[0][hh*8+d], s0);
            s1 = fmaf(v, satt[1][hh*8+d], s1);
            s2 = fmaf(v, satt[2][hh*8+d], s2);
            s3 = fmaf(v, satt[3][hh*8+d], s3);
        }
        al[0][hh] = s0; al[1][hh] = s1; al[2][hh] = s2; al[3][hh] = s3;
    }
    if (ao0) *reinterpret_cast<float4*>(ao0 + (size_t)n*4) = make_float4(al[0][0],al[0][1],al[0][2],al[0][3]);
    if (ao1) *reinterpret_cast<float4*>(ao1 + (size_t)n*4) = make_float4(al[1][0],al[1][1],al[1][2],al[1][3]);
    if (ao2) *reinterpret_cast<float4*>(ao2 + (size_t)n*4) = make_float4(al[2][0],al[2][1],al[2][2],al[2][3]);
    if (ao3) *reinterpret_cast<float4*>(ao3 + (size_t)n*4) = make_float4(al[3][0],al[3][1],al[3][2],al[3][3]);
}

// ---------------------------------------------------------------------------
// Edge pass 1: accumulate softmax denominators (shift-free; logits are O(1))
// ---------------------------------------------------------------------------
__global__ void edge_sum_kernel(const int* __restrict__ src, const int* __restrict__ dst,
                                const float* __restrict__ as, const float* __restrict__ ad,
                                float* __restrict__ ssum, int E)
{
    int e = blockIdx.x * blockDim.x + threadIdx.x;
    if (e >= E) return;
    int s = src[e], d = dst[e];
    float4 a = reinterpret_cast<const float4*>(as)[s];
    float4 b = reinterpret_cast<const float4*>(ad)[d];
    float e0 = __expf(fminf(leaky(a.x + b.x), 70.f));
    float e1 = __expf(fminf(leaky(a.y + b.y), 70.f));
    float e2 = __expf(fminf(leaky(a.z + b.z), 70.f));
    float e3 = __expf(fminf(leaky(a.w + b.w), 70.f));
    atomicAdd4(ssum + (size_t)d * 4, e0, e1, e2, e3);
}

// ---------------------------------------------------------------------------
// Edge pass 2: out[dst] += h_src[src] * alpha   (alpha recomputed)
// ---------------------------------------------------------------------------
__global__ void edge_scatter_kernel(const int* __restrict__ src, const int* __restrict__ dst,
                                    const float* __restrict__ as, const float* __restrict__ ad,
                                    const float* __restrict__ ssum,
                                    const float* __restrict__ hsrc, float* __restrict__ out, int E)
{
    int e = blockIdx.x * blockDim.x + threadIdx.x;
    if (e >= E) return;
    int s = src[e], d = dst[e];
    float4 a  = reinterpret_cast<const float4*>(as)[s];
    float4 b  = reinterpret_cast<const float4*>(ad)[d];
    float4 sv = reinterpret_cast<const float4*>(ssum)[d];
    float w[4];
    w[0] = __expf(fminf(leaky(a.x + b.x), 70.f)) / (sv.x + 1e-16f);
    w[1] = __expf(fminf(leaky(a.y + b.y), 70.f)) / (sv.y + 1e-16f);
    w[2] = __expf(fminf(leaky(a.z + b.z), 70.f)) / (sv.z + 1e-16f);
    w[3] = __expf(fminf(leaky(a.w + b.w), 70.f)) / (sv.w + 1e-16f);
    const float4* hr = reinterpret_cast<const float4*>(hsrc + (size_t)s * HID);
    float* od = out + (size_t)d * HID;
#pragma unroll
    for (int j = 0; j < 8; j++) {
        float4 v = hr[j];
        float ww = w[j >> 1];
        atomicAdd4(od + j * 4, v.x * ww, v.y * ww, v.z * ww, v.w * ww);
    }
}

// ---------------------------------------------------------------------------
// Semantic attention: sums of tanh(relu(o_r) @ kW + kb) over nodes, r in {0,1}
// ---------------------------------------------------------------------------
__global__ void sem_mean_kernel(const float* __restrict__ o1, const float* __restrict__ o2,
                                const float* __restrict__ kW, const float* __restrict__ kb,
                                float* __restrict__ sem, int N)
{
    __shared__ float sW[HID * HID];
    __shared__ float sb[HID];
    __shared__ float sacc[64];
    int tid = threadIdx.x;
    for (int i = tid; i < HID * HID; i += blockDim.x) sW[i] = kW[i];
    if (tid < HID) sb[tid] = kb[tid];
    if (tid < 64) sacc[tid] = 0.f;
    __syncthreads();

    int n = blockIdx.x * blockDim.x + tid;
    bool valid = (n < N);
#pragma unroll
    for (int r = 0; r < 2; r++) {
        const float* o = (r == 0) ? o1 : o2;
        float row[HID];
        if (valid) {
            const float4* rv = reinterpret_cast<const float4*>(o + (size_t)n * HID);
#pragma unroll
            for (int j = 0; j < 8; j++) {
                float4 v = rv[j];
                row[4*j+0] = fmaxf(v.x, 0.f); row[4*j+1] = fmaxf(v.y, 0.f);
                row[4*j+2] = fmaxf(v.z, 0.f); row[4*j+3] = fmaxf(v.w, 0.f);
            }
        } else {
#pragma unroll
            for (int j = 0; j < HID; j++) row[j] = 0.f;
        }
#pragma unroll
        for (int c = 0; c < HID; c++) {
            float acc = sb[c];
#pragma unroll
            for (int k = 0; k < HID; k++) acc = fmaf(row[k], sW[k * HID + c], acc);
            float v = valid ? tanhf(acc) : 0.f;
#pragma unroll
            for (int off = 16; off > 0; off >>= 1)
                v += __shfl_down_sync(0xFFFFFFFFu, v, off);
            if ((tid & 31) == 0) atomicAdd(&sacc[r * HID + c], v);
        }
    }
    __syncthreads();
    if (tid < 64) atomicAdd(&sem[tid], sacc[tid]);
}

__global__ void attn_kernel(const float* __restrict__ sem, const float* __restrict__ q,
                            float* __restrict__ attn, float invN)
{
    __shared__ float sc[2];
    int tid = threadIdx.x; // 64 threads: warp0 -> rel0, warp1 -> rel1
    float v = (sem[tid] * invN) * q[tid & 31];
#pragma unroll
    for (int off = 16; off > 0; off >>= 1)
        v += __shfl_down_sync(0xFFFFFFFFu, v, off);
    if ((tid & 31) == 0) sc[tid >> 5] = v;
    __syncthreads();
    if (tid == 0) {
        float m = fmaxf(sc[0], sc[1]);
        float e0 = __expf(sc[0] - m), e1 = __expf(sc[1] - m);
        float inv = 1.f / (e0 + e1);
        attn[0] = e0 * inv; attn[1] = e1 * inv;
    }
}

__global__ void combine_kernel(const float* __restrict__ o1, const float* __restrict__ o2,
                               const float* __restrict__ attn, float* __restrict__ A, int Ntot)
{
    int i = blockIdx.x * blockDim.x + threadIdx.x;
    if (i >= Ntot) return;
    float a0 = attn[0], a1 = attn[1];
    A[i] = a0 * fmaxf(o1[i], 0.f) + a1 * fmaxf(o2[i], 0.f);
}

__global__ void combine_final_kernel(const float* __restrict__ o1, const float* __restrict__ o2,
                                     const float* __restrict__ attn,
                                     const float* __restrict__ linW, const float* __restrict__ linb,
                                     float* __restrict__ out, int N)
{
    __shared__ float sw[64];
    __shared__ float sb2[2];
    int tid = threadIdx.x;
    if (tid < 64) sw[tid] = linW[tid];
    if (tid < 2)  sb2[tid] = linb[tid];
    __syncthreads();
    int n = blockIdx.x * blockDim.x + tid;
    if (n >= N) return;
    float a0 = attn[0], a1 = attn[1];
    float s0 = sb2[0], s1 = sb2[1];
    const float4* r1 = reinterpret_cast<const float4*>(o1 + (size_t)n * HID);
    const float4* r2 = reinterpret_cast<const float4*>(o2 + (size_t)n * HID);
#pragma unroll
    for (int j = 0; j < 8; j++) {
        float4 v1 = r1[j], v2 = r2[j];
        float c;
        c = a0*fmaxf(v1.x,0.f) + a1*fmaxf(v2.x,0.f); s0 = fmaf(c, sw[(4*j+0)*2+0], s0); s1 = fmaf(c, sw[(4*j+0)*2+1], s1);
        c = a0*fmaxf(v1.y,0.f) + a1*fmaxf(v2.y,0.f); s0 = fmaf(c, sw[(4*j+1)*2+0], s0); s1 = fmaf(c, sw[(4*j+1)*2+1], s1);
        c = a0*fmaxf(v1.z,0.f) + a1*fmaxf(v2.z,0.f); s0 = fmaf(c, sw[(4*j+2)*2+0], s0); s1 = fmaf(c, sw[(4*j+2)*2+1], s1);
        c = a0*fmaxf(v1.w,0.f) + a1*fmaxf(v2.w,0.f); s0 = fmaf(c, sw[(4*j+3)*2+0], s0); s1 = fmaf(c, sw[(4*j+3)*2+1], s1);
    }
    out[n * 2 + 0] = s0;
    out[n * 2 + 1] = s1;
}

// ---------------------------------------------------------------------------
// Host orchestration
// ---------------------------------------------------------------------------
static void launch_layer(const float* xa, const float* xt, int Fin, int relu_t,
                         const float* Wa, const float* ba, const float* Wt, const float* bt,
                         const float* attS, const float* attD,   // layer base [3][4][8]
                         const float* kW, const float* kb, const float* qv,
                         const int* eat_s, const int* eat_d,
                         const int* eta_s, const int* eta_d,
                         const int* eaa_s, const int* eaa_d,
                         Scratch* S, bool with_tx,
                         const float* linW, const float* linb, float* out)
{
    int nba = (N_ADDR + TB - 1) / TB;
    int nbt = (N_TX   + TB - 1) / TB;

    proj_kernel<<<nba, TB>>>(xa, N_ADDR, Fin, Wa, ba, S->ha,
        with_tx ? attS + 0 : (const float*)nullptr, with_tx ? S->as_at : (float*)nullptr,
        attD + 32, S->ad_ta,
        attS + 64, S->as_aa,
        attD + 64, S->ad_aa, 0);
    proj_kernel<<<nbt, TB>>>(xt, N_TX, Fin, Wt, bt, S->ht,
        with_tx ? attD + 0 : (const float*)nullptr, with_tx ? S->ad_at : (float*)nullptr,
        attS + 32, S->as_ta,
        nullptr, nullptr, nullptr, nullptr, relu_t);

    if (with_tx) {
        cudaMemsetAsync(S->s_tx, 0, sizeof(float) * N_TX * 4);
        cudaMemsetAsync(S->otx,  0, sizeof(float) * (size_t)N_TX * HID);
    }
    cudaMemsetAsync(S->s_a1, 0, sizeof(float) * N_ADDR * 4);
    cudaMemsetAsync(S->s_a2, 0, sizeof(float) * N_ADDR * 4);
    cudaMemsetAsync(S->oa1,  0, sizeof(float) * (size_t)N_ADDR * HID);
    cudaMemsetAsync(S->oa2,  0, sizeof(float) * (size_t)N_ADDR * HID);
    cudaMemsetAsync(S->sem,  0, sizeof(float) * 64);

    int nb_at = (E_AT + TB - 1) / TB;
    int nb_ta = (E_TA + TB - 1) / TB;
    int nb_aa = (E_AA + TB - 1) / TB;

    if (with_tx)
        edge_sum_kernel<<<nb_at, TB>>>(eat_s, eat_d, S->as_at, S->ad_at, S->s_tx, E_AT);
    edge_sum_kernel<<<nb_ta, TB>>>(eta_s, eta_d, S->as_ta, S->ad_ta, S->s_a1, E_TA);
    edge_sum_kernel<<<nb_aa, TB>>>(eaa_s, eaa_d, S->as_aa, S->ad_aa, S->s_a2, E_AA);

    if (with_tx)
        edge_scatter_kernel<<<nb_at, TB>>>(eat_s, eat_d, S->as_at, S->ad_at, S->s_tx, S->ha, S->otx, E_AT);
    edge_scatter_kernel<<<nb_ta, TB>>>(eta_s, eta_d, S->as_ta, S->ad_ta, S->s_a1, S->ht, S->oa1, E_TA);
    edge_scatter_kernel<<<nb_aa, TB>>>(eaa_s, eaa_d, S->as_aa, S->ad_aa, S->s_a2, S->ha, S->oa2, E_AA);

    sem_mean_kernel<<<nba, TB>>>(S->oa1, S->oa2, kW, kb, S->sem, N_ADDR);
    attn_kernel<<<1, 64>>>(S->sem, qv, S->attn, 1.f / (float)N_ADDR);

    if (out) {
        combine_final_kernel<<<nba, TB>>>(S->oa1, S->oa2, S->attn, linW, linb, out, N_ADDR);
    } else {
        int nbc = (N_ADDR * HID + TB - 1) / TB;
        combine_kernel<<<nbc, TB>>>(S->oa1, S->oa2, S->attn, S->A, N_ADDR * HID);
    }
}

extern "C" void kernel_launch(void* const* d_in, const int* in_sizes, int n_in,
                              void* d_out, int out_size)
{
    const float* x_addr  = (const float*)d_in[0];
    const float* x_tx    = (const float*)d_in[1];
    const int*   eat_s   = (const int*)d_in[2];
    const int*   eat_d   = (const int*)d_in[3];
    const int*   eta_s   = (const int*)d_in[4];
    const int*   eta_d   = (const int*)d_in[5];
    const int*   eaa_s   = (const int*)d_in[6];
    const int*   eaa_d   = (const int*)d_in[7];
    const float* pW1     = (const float*)d_in[8];    // [2,64,32]
    const float* pb1     = (const float*)d_in[9];    // [2,32]
    const float* pW23    = (const float*)d_in[10];   // [2,2,32,32]
    const float* pb23    = (const float*)d_in[11];   // [2,2,32]
    const float* att_src = (const float*)d_in[12];   // [3,3,4,8]
    const float* att_dst = (const float*)d_in[13];
    const float* kW      = (const float*)d_in[14];   // [3,32,32]
    const float* kb      = (const float*)d_in[15];   // [3,32]
    const float* q       = (const float*)d_in[16];   // [3,32]
    const float* linW    = (const float*)d_in[17];   // [32,2]
    const float* linb    = (const float*)d_in[18];   // [2]
    float* out = (float*)d_out;

    Scratch* S = nullptr;
    cudaGetSymbolAddress((void**)&S, g_scr);

    // Layer 1 (Fin=64, raw inputs)
    launch_layer(x_addr, x_tx, 64, 0,
                 pW1 + 0, pb1 + 0, pW1 + 64 * 32, pb1 + 32,
                 att_src + 0,  att_dst + 0,
                 kW + 0, kb + 0, q + 0,
                 eat_s, eat_d, eta_s, eta_d, eaa_s, eaa_d,
                 S, true, nullptr, nullptr, nullptr);

    // Layer 2 (Fin=32): addr in = A (already >=0), tx in = relu(otx)
    launch_layer(S->A, S->otx, 32, 1,
                 pW23 + 0 * 1024, pb23 + 0, pW23 + 1 * 1024, pb23 + 32,
                 att_src + 96, att_dst + 96,
                 kW + 1024, kb + 32, q + 32,
                 eat_s, eat_d, eta_s, eta_d, eaa_s, eaa_d,
                 S, true, nullptr, nullptr, nullptr);

    // Layer 3: tx outputs are dead -> skip relation at and tx semantic; fuse final linear
    launch_layer(S->A, S->otx, 32, 1,
                 pW23 + 2 * 1024, pb23 + 64, pW23 + 3 * 1024, pb23 + 96,
                 att_src + 192, att_dst + 192,
                 kW + 2048, kb + 64, q + 64,
                 eat_s, eat_d, eta_s, eta_d, eaa_s, eaa_d,
                 S, false, linW, linb, out);

    (void)in_sizes; (void)n_in; (void)out_size;
}

// round 2
// speedup vs baseline: 1.1162x; 1.1162x over previous
#include <cuda_runtime.h>
#include <math.h>

#define N_ADDR 150000
#define N_TX   200000
#define HID    32
#define E_AT   1000000
#define E_TA   1000000
#define E_AA   500000
#define SLOPE  0.2f
#define TB     256
#define SCAN_T 1024

// ---------------------------------------------------------------------------
// Scratch (device global — no runtime allocation)
// ---------------------------------------------------------------------------
struct __align__(128) Scratch {
    float ha [N_ADDR * HID];
    float ht [N_TX   * HID];
    float A  [N_ADDR * HID];
    float otx[N_TX   * HID];
    float oa1[N_ADDR * HID];
    float oa2[N_ADDR * HID];
    float as_at[N_ADDR * 4];
    float ad_at[N_TX   * 4];
    float as_ta[N_TX   * 4];
    float ad_ta[N_ADDR * 4];
    float as_aa[N_ADDR * 4];
    float ad_aa[N_ADDR * 4];
    float sem[64];
    float attn[2];
    // CSR (by destination) for the three edge types
    int cnt_at[N_TX];   int cur_at[N_TX];   int rs_at[N_TX];   int col_at[E_AT];
    int cnt_ta[N_ADDR]; int cur_ta[N_ADDR]; int rs_ta[N_ADDR]; int col_ta[E_TA];
    int cnt_aa[N_ADDR]; int cur_aa[N_ADDR]; int rs_aa[N_ADDR]; int col_aa[E_AA];
    int bsums[512];
};
__device__ Scratch g_scr;

__device__ __forceinline__ float leaky(float v) { return v >= 0.f ? v : SLOPE * v; }

// ---------------------------------------------------------------------------
// CSR build
// ---------------------------------------------------------------------------
__global__ void hist_kernel(const int* __restrict__ dst, int E, int* __restrict__ cnt)
{
    int e = blockIdx.x * blockDim.x + threadIdx.x;
    if (e < E) atomicAdd(&cnt[dst[e]], 1);
}

__global__ void scan_reduce_kernel(const int* __restrict__ cnt, int n, int* __restrict__ bsums)
{
    __shared__ int sd[SCAN_T];
    int tid = threadIdx.x;
    int i = blockIdx.x * SCAN_T + tid;
    sd[tid] = (i < n) ? cnt[i] : 0;
    __syncthreads();
#pragma unroll
    for (int off = SCAN_T / 2; off > 0; off >>= 1) {
        if (tid < off) sd[tid] += sd[tid + off];
        __syncthreads();
    }
    if (tid == 0) bsums[blockIdx.x] = sd[0];
}

__global__ void scan_bsums_kernel(int* __restrict__ bsums, int nb)
{
    __shared__ int sd[512];
    int tid = threadIdx.x;
    sd[tid] = (tid < nb) ? bsums[tid] : 0;
    __syncthreads();
    if (tid == 0) {
        int run = 0;
        for (int i = 0; i < nb; i++) { int t = sd[i]; sd[i] = run; run += t; }
    }
    __syncthreads();
    if (tid < nb) bsums[tid] = sd[tid];
}

__global__ void scan_apply_kernel(const int* __restrict__ cnt, int* __restrict__ rs,
                                  const int* __restrict__ bsums, int n)
{
    __shared__ int sd[SCAN_T];
    int tid = threadIdx.x;
    int i = blockIdx.x * SCAN_T + tid;
    int v = (i < n) ? cnt[i] : 0;
    sd[tid] = v;
    __syncthreads();
#pragma unroll
    for (int off = 1; off < SCAN_T; off <<= 1) {
        int t = (tid >= off) ? sd[tid - off] : 0;
        __syncthreads();
        sd[tid] += t;
        __syncthreads();
    }
    if (i < n) rs[i] = sd[tid] - v + bsums[blockIdx.x];
}

__global__ void fill_kernel(const int* __restrict__ src, const int* __restrict__ dst, int E,
                            const int* __restrict__ rs, int* __restrict__ cur,
                            int* __restrict__ col)
{
    int e = blockIdx.x * blockDim.x + threadIdx.x;
    if (e >= E) return;
    int d = dst[e];
    int pos = rs[d] + atomicAdd(&cur[d], 1);
    col[pos] = src[e];
}

// ---------------------------------------------------------------------------
// Projection: h = (relu?)x @ W + b; fused alpha dot-products (up to 4)
// ---------------------------------------------------------------------------
__global__ void proj_kernel(const float* __restrict__ x, int N, int Fin,
                            const float* __restrict__ W, const float* __restrict__ b,
                            float* __restrict__ h,
                            const float* __restrict__ att0, float* __restrict__ ao0,
                            const float* __restrict__ att1, float* __restrict__ ao1,
                            const float* __restrict__ att2, float* __restrict__ ao2,
                            const float* __restrict__ att3, float* __restrict__ ao3,
                            int relu_in)
{
    __shared__ float sW[64 * HID];
    __shared__ float sb[HID];
    __shared__ float satt[4][HID];
    int tid = threadIdx.x;
    for (int i = tid; i < Fin * HID; i += blockDim.x) sW[i] = W[i];
    if (tid < HID) {
        sb[tid]      = b[tid];
        satt[0][tid] = att0 ? att0[tid] : 0.f;
        satt[1][tid] = att1 ? att1[tid] : 0.f;
        satt[2][tid] = att2 ? att2[tid] : 0.f;
        satt[3][tid] = att3 ? att3[tid] : 0.f;
    }
    __syncthreads();
    int n = blockIdx.x * blockDim.x + tid;
    if (n >= N) return;

    float acc[HID];
#pragma unroll
    for (int c = 0; c < HID; c++) acc[c] = sb[c];
    const float* xr = x + (size_t)n * Fin;
    for (int k = 0; k < Fin; k++) {
        float xv = xr[k];
        if (relu_in) xv = fmaxf(xv, 0.f);
#pragma unroll
        for (int c = 0; c < HID; c++) acc[c] = fmaf(xv, sW[k * HID + c], acc[c]);
    }
    float4* hv = reinterpret_cast<float4*>(h + (size_t)n * HID);
#pragma unroll
    for (int j = 0; j < 8; j++)
        hv[j] = make_float4(acc[4*j], acc[4*j+1], acc[4*j+2], acc[4*j+3]);

    float al[4][4];
#pragma unroll
    for (int hh = 0; hh < 4; hh++) {
        float s0 = 0.f, s1 = 0.f, s2 = 0.f, s3 = 0.f;
#pragma unroll
        for (int d = 0; d < 8; d++) {
            float v = acc[hh * 8 + d];
            s0 = fmaf(v, satt[0][hh*8+d], s0);
            s1 = fmaf(v, satt[1][hh*8+d], s1);
            s2 = fmaf(v, satt[2][hh*8+d], s2);
            s3 = fmaf(v, satt[3][hh*8+d], s3);
        }
        al[0][hh] = s0; al[1][hh] = s1; al[2][hh] = s2; al[3][hh] = s3;
    }
    if (ao0) *reinterpret_cast<float4*>(ao0 + (size_t)n*4) = make_float4(al[0][0],al[0][1],al[0][2],al[0][3]);
    if (ao1) *reinterpret_cast<float4*>(ao1 + (size_t)n*4) = make_float4(al[1][0],al[1][1],al[1][2],al[1][3]);
    if (ao2) *reinterpret_cast<float4*>(ao2 + (size_t)n*4) = make_float4(al[2][0],al[2][1],al[2][2],al[2][3]);
    if (ao3) *reinterpret_cast<float4*>(ao3 + (size_t)n*4) = make_float4(al[3][0],al[3][1],al[3][2],al[3][3]);
}

// ---------------------------------------------------------------------------
// Single-pass CSR relation gather: warp per dst node, lane = channel.
// out[d] = sum_e(exp(leaky(as[s]+ad[d])) * h_src[s]) / (sum_e exp + 1e-16)
// ---------------------------------------------------------------------------
__global__ void relation_gather(const int* __restrict__ rs, const int* __restrict__ cnt,
                                const int* __restrict__ col,
                                const float* __restrict__ as, const float* __restrict__ ad,
                                const float* __restrict__ hsrc, float* __restrict__ out,
                                int Ndst)
{
    int w = (blockIdx.x * blockDim.x + threadIdx.x) >> 5;
    int lane = threadIdx.x & 31;
    if (w >= Ndst) return;
    int head = lane >> 3;
    float adv = ad[(size_t)w * 4 + head];
    int start = rs[w];
    int n = cnt[w];
    float acc = 0.f, ds = 0.f;
    if (n > 0) {
        int   s   = col[start];
        float asv = as[s * 4 + head];
        float v   = hsrc[(size_t)s * HID + lane];
        for (int j = 1; j < n; j++) {
            int   s2   = col[start + j];
            float asv2 = as[s2 * 4 + head];
            float v2   = hsrc[(size_t)s2 * HID + lane];
            float wgt = __expf(fminf(leaky(asv + adv), 70.f));
            acc = fmaf(v, wgt, acc);
            ds += wgt;
            asv = asv2; v = v2;
        }
        float wgt = __expf(fminf(leaky(asv + adv), 70.f));
        acc = fmaf(v, wgt, acc);
        ds += wgt;
    }
    out[(size_t)w * HID + lane] = acc / (ds + 1e-16f);
}

// ---------------------------------------------------------------------------
// Semantic attention
// ---------------------------------------------------------------------------
__global__ void sem_mean_kernel(const float* __restrict__ o1, const float* __restrict__ o2,
                                const float* __restrict__ kW, const float* __restrict__ kb,
                                float* __restrict__ sem, int N)
{
    __shared__ float sW[HID * HID];
    __shared__ float sb[HID];
    __shared__ float sacc[64];
    int tid = threadIdx.x;
    for (int i = tid; i < HID * HID; i += blockDim.x) sW[i] = kW[i];
    if (tid < HID) sb[tid] = kb[tid];
    if (tid < 64) sacc[tid] = 0.f;
    __syncthreads();

    int n = blockIdx.x * blockDim.x + tid;
    bool valid = (n < N);
#pragma unroll
    for (int r = 0; r < 2; r++) {
        const float* o = (r == 0) ? o1 : o2;
        float row[HID];
        if (valid) {
            const float4* rv = reinterpret_cast<const float4*>(o + (size_t)n * HID);
#pragma unroll
            for (int j = 0; j < 8; j++) {
                float4 v = rv[j];
                row[4*j+0] = fmaxf(v.x, 0.f); row[4*j+1] = fmaxf(v.y, 0.f);
                row[4*j+2] = fmaxf(v.z, 0.f); row[4*j+3] = fmaxf(v.w, 0.f);
            }
        } else {
#pragma unroll
            for (int j = 0; j < HID; j++) row[j] = 0.f;
        }
#pragma unroll
        for (int c = 0; c < HID; c++) {
            float acc = sb[c];
#pragma unroll
            for (int k = 0; k < HID; k++) acc = fmaf(row[k], sW[k * HID + c], acc);
            float v = valid ? tanhf(acc) : 0.f;
#pragma unroll
            for (int off = 16; off > 0; off >>= 1)
                v += __shfl_down_sync(0xFFFFFFFFu, v, off);
            if ((tid & 31) == 0) atomicAdd(&sacc[r * HID + c], v);
        }
    }
    __syncthreads();
    if (tid < 64) atomicAdd(&sem[tid], sacc[tid]);
}

__global__ void attn_kernel(const float* __restrict__ sem, const float* __restrict__ q,
                            float* __restrict__ attn, float invN)
{
    __shared__ float sc[2];
    int tid = threadIdx.x;
    float v = (sem[tid] * invN) * q[tid & 31];
#pragma unroll
    for (int off = 16; off > 0; off >>= 1)
        v += __shfl_down_sync(0xFFFFFFFFu, v, off);
    if ((tid & 31) == 0) sc[tid >> 5] = v;
    __syncthreads();
    if (tid == 0) {
        float m = fmaxf(sc[0], sc[1]);
        float e0 = __expf(sc[0] - m), e1 = __expf(sc[1] - m);
        float inv = 1.f / (e0 + e1);
        attn[0] = e0 * inv; attn[1] = e1 * inv;
    }
}

__global__ void combine_kernel(const float* __restrict__ o1, const float* __restrict__ o2,
                               const float* __restrict__ attn, float* __restrict__ A, int Ntot)
{
    int i = blockIdx.x * blockDim.x + threadIdx.x;
    if (i >= Ntot) return;
    float a0 = attn[0], a1 = attn[1];
    A[i] = a0 * fmaxf(o1[i], 0.f) + a1 * fmaxf(o2[i], 0.f);
}

__global__ void combine_final_kernel(const float* __restrict__ o1, const float* __restrict__ o2,
                                     const float* __restrict__ attn,
                                     const float* __restrict__ linW, const float* __restrict__ linb,
                                     float* __restrict__ out, int N)
{
    __shared__ float sw[64];
    __shared__ float sb2[2];
    int tid = threadIdx.x;
    if (tid < 64) sw[tid] = linW[tid];
    if (tid < 2)  sb2[tid] = linb[tid];
    __syncthreads();
    int n = blockIdx.x * blockDim.x + tid;
    if (n >= N) return;
    float a0 = attn[0], a1 = attn[1];
    float s0 = sb2[0], s1 = sb2[1];
    const float4* r1 = reinterpret_cast<const float4*>(o1 + (size_t)n * HID);
    const float4* r2 = reinterpret_cast<const float4*>(o2 + (size_t)n * HID);
#pragma unroll
    for (int j = 0; j < 8; j++) {
        float4 v1 = r1[j], v2 = r2[j];
        float c;
        c = a0*fmaxf(v1.x,0.f) + a1*fmaxf(v2.x,0.f); s0 = fmaf(c, sw[(4*j+0)*2+0], s0); s1 = fmaf(c, sw[(4*j+0)*2+1], s1);
        c = a0*fmaxf(v1.y,0.f) + a1*fmaxf(v2.y,0.f); s0 = fmaf(c, sw[(4*j+1)*2+0], s0); s1 = fmaf(c, sw[(4*j+1)*2+1], s1);
        c = a0*fmaxf(v1.z,0.f) + a1*fmaxf(v2.z,0.f); s0 = fmaf(c, sw[(4*j+2)*2+0], s0); s1 = fmaf(c, sw[(4*j+2)*2+1], s1);
        c = a0*fmaxf(v1.w,0.f) + a1*fmaxf(v2.w,0.f); s0 = fmaf(c, sw[(4*j+3)*2+0], s0); s1 = fmaf(c, sw[(4*j+3)*2+1], s1);
    }
    out[n * 2 + 0] = s0;
    out[n * 2 + 1] = s1;
}

// ---------------------------------------------------------------------------
// Host orchestration
// ---------------------------------------------------------------------------
static void build_csr(const int* src, const int* dst, int E, int N,
                      int* cnt, int* cur, int* rs, int* col, int* bsums)
{
    cudaMemsetAsync(cnt, 0, sizeof(int) * N);
    cudaMemsetAsync(cur, 0, sizeof(int) * N);
    hist_kernel<<<(E + TB - 1) / TB, TB>>>(dst, E, cnt);
    int nb = (N + SCAN_T - 1) / SCAN_T;
    scan_reduce_kernel<<<nb, SCAN_T>>>(cnt, N, bsums);
    scan_bsums_kernel<<<1, 512>>>(bsums, nb);
    scan_apply_kernel<<<nb, SCAN_T>>>(cnt, rs, bsums, N);
    fill_kernel<<<(E + TB - 1) / TB, TB>>>(src, dst, E, rs, cur, col);
}

static void launch_layer(const float* xa, const float* xt, int Fin, int relu_t,
                         const float* Wa, const float* ba, const float* Wt, const float* bt,
                         const float* attS, const float* attD,
                         const float* kW, const float* kb, const float* qv,
                         Scratch* S, bool with_tx,
                         const float* linW, const float* linb, float* out)
{
    int nba = (N_ADDR + TB - 1) / TB;
    int nbt = (N_TX   + TB - 1) / TB;

    proj_kernel<<<nba, TB>>>(xa, N_ADDR, Fin, Wa, ba, S->ha,
        with_tx ? attS + 0 : (const float*)nullptr, with_tx ? S->as_at : (float*)nullptr,
        attD + 32, S->ad_ta,
        attS + 64, S->as_aa,
        attD + 64, S->ad_aa, 0);
    proj_kernel<<<nbt, TB>>>(xt, N_TX, Fin, Wt, bt, S->ht,
        with_tx ? attD + 0 : (const float*)nullptr, with_tx ? S->ad_at : (float*)nullptr,
        attS + 32, S->as_ta,
        nullptr, nullptr, nullptr, nullptr, relu_t);

    cudaMemsetAsync(S->sem, 0, sizeof(float) * 64);

    int gb_tx = (N_TX   * 32 + TB - 1) / TB;
    int gb_a  = (N_ADDR * 32 + TB - 1) / TB;

    if (with_tx)
        relation_gather<<<gb_tx, TB>>>(S->rs_at, S->cnt_at, S->col_at,
                                       S->as_at, S->ad_at, S->ha, S->otx, N_TX);
    relation_gather<<<gb_a, TB>>>(S->rs_ta, S->cnt_ta, S->col_ta,
                                  S->as_ta, S->ad_ta, S->ht, S->oa1, N_ADDR);
    relation_gather<<<gb_a, TB>>>(S->rs_aa, S->cnt_aa, S->col_aa,
                                  S->as_aa, S->ad_aa, S->ha, S->oa2, N_ADDR);

    sem_mean_kernel<<<nba, TB>>>(S->oa1, S->oa2, kW, kb, S->sem, N_ADDR);
    attn_kernel<<<1, 64>>>(S->sem, qv, S->attn, 1.f / (float)N_ADDR);

    if (out) {
        combine_final_kernel<<<nba, TB>>>(S->oa1, S->oa2, S->attn, linW, linb, out, N_ADDR);
    } else {
        int nbc = (N_ADDR * HID + TB - 1) / TB;
        combine_kernel<<<nbc, TB>>>(S->oa1, S->oa2, S->attn, S->A, N_ADDR * HID);
    }
}

extern "C" void kernel_launch(void* const* d_in, const int* in_sizes, int n_in,
                              void* d_out, int out_size)
{
    const float* x_addr  = (const float*)d_in[0];
    const float* x_tx    = (const float*)d_in[1];
    const int*   eat_s   = (const int*)d_in[2];
    const int*   eat_d   = (const int*)d_in[3];
    const int*   eta_s   = (const int*)d_in[4];
    const int*   eta_d   = (const int*)d_in[5];
    const int*   eaa_s   = (const int*)d_in[6];
    const int*   eaa_d   = (const int*)d_in[7];
    const float* pW1     = (const float*)d_in[8];
    const float* pb1     = (const float*)d_in[9];
    const float* pW23    = (const float*)d_in[10];
    const float* pb23    = (const float*)d_in[11];
    const float* att_src = (const float*)d_in[12];
    const float* att_dst = (const float*)d_in[13];
    const float* kW      = (const float*)d_in[14];
    const float* kb      = (const float*)d_in[15];
    const float* q       = (const float*)d_in[16];
    const float* linW    = (const float*)d_in[17];
    const float* linb    = (const float*)d_in[18];
    float* out = (float*)d_out;

    Scratch* S = nullptr;
    cudaGetSymbolAddress((void**)&S, g_scr);

    // Build dst-CSR for each edge type (reused by all 3 layers)
    build_csr(eat_s, eat_d, E_AT, N_TX,   S->cnt_at, S->cur_at, S->rs_at, S->col_at, S->bsums);
    build_csr(eta_s, eta_d, E_TA, N_ADDR, S->cnt_ta, S->cur_ta, S->rs_ta, S->col_ta, S->bsums);
    build_csr(eaa_s, eaa_d, E_AA, N_ADDR, S->cnt_aa, S->cur_aa, S->rs_aa, S->col_aa, S->bsums);

    // Layer 1 (Fin=64)
    launch_layer(x_addr, x_tx, 64, 0,
                 pW1 + 0, pb1 + 0, pW1 + 64 * 32, pb1 + 32,
                 att_src + 0,  att_dst + 0,
                 kW + 0, kb + 0, q + 0,
                 S, true, nullptr, nullptr, nullptr);

    // Layer 2 (Fin=32)
    launch_layer(S->A, S->otx, 32, 1,
                 pW23 + 0 * 1024, pb23 + 0, pW23 + 1 * 1024, pb23 + 32,
                 att_src + 96, att_dst + 96,
                 kW + 1024, kb + 32, q + 32,
                 S, true, nullptr, nullptr, nullptr);

    // Layer 3: tx outputs dead -> skip at relation; fuse final linear
    launch_layer(S->A, S->otx, 32, 1,
                 pW23 + 2 * 1024, pb23 + 64, pW23 + 3 * 1024, pb23 + 96,
                 att_src + 192, att_dst + 192,
                 kW + 2048, kb + 64, q + 64,
                 S, false, linW, linb, out);

    (void)in_sizes; (void)n_in; (void)out_size;
}